// round 16
// baseline (speedup 1.0000x reference)
#include <cuda_runtime.h>
#include <cstdint>

typedef unsigned long long u64;

// ---- packed f32x2 helpers (Blackwell sm_100+; FFMA2 only reachable via PTX) ----
__device__ __forceinline__ u64 pack2(float lo, float hi) {
    u64 r; asm("mov.b64 %0, {%1, %2};" : "=l"(r) : "f"(lo), "f"(hi)); return r;
}
__device__ __forceinline__ void unpack2(u64 v, float& lo, float& hi) {
    asm("mov.b64 {%0, %1}, %2;" : "=f"(lo), "=f"(hi) : "l"(v));
}
__device__ __forceinline__ u64 sub2(u64 a, u64 b) {
    u64 r; asm("sub.rn.f32x2 %0, %1, %2;" : "=l"(r) : "l"(a), "l"(b)); return r;
}
__device__ __forceinline__ u64 add2(u64 a, u64 b) {
    u64 r; asm("add.rn.f32x2 %0, %1, %2;" : "=l"(r) : "l"(a), "l"(b)); return r;
}
__device__ __forceinline__ u64 fma2(u64 a, u64 b, u64 c) {
    u64 r; asm("fma.rn.f32x2 %0, %1, %2, %3;" : "=l"(r) : "l"(a), "l"(b), "l"(c)); return r;
}

#define L_PATH 256
#define D_CH   8
#define OUT_B  584   // 8 + 64 + 512
#define SLOT   584   // slot: S1 @0, S2 @8 ([i][j] row-major), S3 @72 ([p][k], p=8i+j)
#define NTHREADS 128
#define SDX_STRIDE 2048          // 255 dx rows + 1 zero pad row = 256*8 floats

// Chen combine: A <- A (x) B, B read from a shared-memory slot.
__device__ __forceinline__ void chen_combine(
    const float* s, int lane, int i, int j0,
    u64 S30[4], u64 S31[4], u64& S2p, u64 S1p[4], float& S1ai)
{
    float S2a0, S2a1; unpack2(S2p, S2a0, S2a1);
    const u64 S2a0p = pack2(S2a0, S2a0);
    const u64 S2a1p = pack2(S2a1, S2a1);
    const u64 S1aip = pack2(S1ai, S1ai);

    ulonglong2 t0 = *reinterpret_cast<const ulonglong2*>(s);
    ulonglong2 t1 = *reinterpret_cast<const ulonglong2*>(s + 4);
    u64 S1bp[4] = {t0.x, t0.y, t1.x, t1.y};

    const float* rj = s + 8 + j0 * 8;
    ulonglong2 u0 = *reinterpret_cast<const ulonglong2*>(rj);
    ulonglong2 u1 = *reinterpret_cast<const ulonglong2*>(rj + 4);
    ulonglong2 v0 = *reinterpret_cast<const ulonglong2*>(rj + 8);
    ulonglong2 v1 = *reinterpret_cast<const ulonglong2*>(rj + 12);
    u64 Bj0[4] = {u0.x, u0.y, u1.x, u1.y};
    u64 Bj1[4] = {v0.x, v0.y, v1.x, v1.y};

    float2 s2bi = *reinterpret_cast<const float2*>(s + 8 + i * 8 + j0);
    float2 s1bj = *reinterpret_cast<const float2*>(s + j0);
    float  s1bi = s[i];

    const float* q = s + 72 + 16 * lane;
    ulonglong2 q0 = *reinterpret_cast<const ulonglong2*>(q);
    ulonglong2 q1 = *reinterpret_cast<const ulonglong2*>(q + 4);
    ulonglong2 q2 = *reinterpret_cast<const ulonglong2*>(q + 8);
    ulonglong2 q3 = *reinterpret_cast<const ulonglong2*>(q + 12);
    u64 Q0[4] = {q0.x, q0.y, q1.x, q1.y};
    u64 Q1[4] = {q2.x, q2.y, q3.x, q3.y};

    // S3 = S3a + S3b + S2a (x) S1b + S1a (x) S2b   (pre-update S2a, S1a)
    #pragma unroll
    for (int kk = 0; kk < 4; ++kk) {
        S30[kk] = add2(S30[kk], Q0[kk]);
        S30[kk] = fma2(S2a0p, S1bp[kk], S30[kk]);
        S30[kk] = fma2(S1aip, Bj0[kk], S30[kk]);
        S31[kk] = add2(S31[kk], Q1[kk]);
        S31[kk] = fma2(S2a1p, S1bp[kk], S31[kk]);
        S31[kk] = fma2(S1aip, Bj1[kk], S31[kk]);
    }
    S2p = add2(S2p, pack2(s2bi.x, s2bi.y));
    S2p = fma2(S1aip, pack2(s1bj.x, s1bj.y), S2p);
    #pragma unroll
    for (int kk = 0; kk < 4; ++kk) S1p[kk] = add2(S1p[kk], S1bp[kk]);
    S1ai += s1bi;
}

__device__ __forceinline__ void write_sig(
    float* s, int lane,
    const u64 S30[4], const u64 S31[4], u64 S2p, const u64 S1p[4])
{
    if (lane == 0) {
        *reinterpret_cast<ulonglong2*>(s)     = make_ulonglong2(S1p[0], S1p[1]);
        *reinterpret_cast<ulonglong2*>(s + 4) = make_ulonglong2(S1p[2], S1p[3]);
    }
    *reinterpret_cast<u64*>(s + 8 + 2 * lane) = S2p;
    float* q = s + 72 + 16 * lane;
    *reinterpret_cast<ulonglong2*>(q)      = make_ulonglong2(S30[0], S30[1]);
    *reinterpret_cast<ulonglong2*>(q + 4)  = make_ulonglong2(S30[2], S30[3]);
    *reinterpret_cast<ulonglong2*>(q + 8)  = make_ulonglong2(S31[0], S31[1]);
    *reinterpret_cast<ulonglong2*>(q + 12) = make_ulonglong2(S31[2], S31[3]);
}

// 128 threads = 4 warps = 1 path split into 4 chunks of 64 steps
// (row 255 is a staged zero row -> identity Chen step, uniform trip count).
// Hot loop: 12 FFMA2 + 3 LDS per step; dxj extracted from row regs (alu SELs).
__global__ void __launch_bounds__(NTHREADS, 8)
logsig_kernel(const float* __restrict__ x, float* __restrict__ out, int B)
{
    __shared__ float sdx[SDX_STRIDE];    // 8 KB: dx rows for this path (+ zero row)
    __shared__ float slots[2][SLOT];     // 4.7 KB: combine slots

    const int tid   = threadIdx.x;
    const int chunk = tid >> 5;          // warp == chunk 0..3
    const int lane  = tid & 31;
    const int i  = lane >> 2;
    const int j0 = (lane & 3) << 1;
    const bool jsel0 = (lane & 1) != 0;  // dxj select predicates (hoisted)
    const bool jsel1 = (lane & 2) != 0;

    const float* __restrict__ xp = x + (size_t)blockIdx.x * (L_PATH * D_CH);

    // ============ stage increments dx[t] = x[t+1]-x[t] into smem (coalesced) ============
    #pragma unroll
    for (int q = 0; q < 4; ++q) {
        int r = tid + q * NTHREADS;       // 0..509 (last iter partially masked)
        if (r < 510) {
            int t = r >> 1;
            int h = (r & 1) << 2;
            const float* src = xp + t * 8 + h;
            float4 b = *reinterpret_cast<const float4*>(src + 8);
            float4 a = *reinterpret_cast<const float4*>(src);
            *reinterpret_cast<float4*>(&sdx[t * 8 + h]) =
                make_float4(b.x - a.x, b.y - a.y, b.z - a.z, b.w - a.w);
        }
    }
    if (tid < 2)                          // zero pad row t=255 (identity step)
        *reinterpret_cast<float4*>(&sdx[2040 + tid * 4]) = make_float4(0.f, 0.f, 0.f, 0.f);
    __syncthreads();

    // ======================= chunk signature (Chen recursion) =======================
    const int first = chunk * 64;
    const float* sp = &sdx[first * 8];

    // HS = (0.5*S1_i, S1_i) packed: one register holds the whole scalar side chain.
    const u64 C_M_A = pack2(1.0f/6.0f, 0.5f);   // MA = (m, a) = (h+dxi/6, S1+dxi/2)
    const u64 C_UPD = pack2(0.5f, 1.0f);        // HS += (0.5, 1)*dxi
    u64 HS    = 0ull;
    u64 S2p   = 0ull;
    u64 S30[4] = {0ull,0ull,0ull,0ull};
    u64 S31[4] = {0ull,0ull,0ull,0ull};

    #pragma unroll 4
    for (int t = 0; t < 64; ++t) {
        const float* row = sp + t * 8;
        ulonglong2 d01 = *reinterpret_cast<const ulonglong2*>(row);
        ulonglong2 d23 = *reinterpret_cast<const ulonglong2*>(row + 4);
        float dxi = row[i];                           // LDS.32 (1 wavefront)

        // dxj = (row[j0], row[j0+1]) — one of the four loaded u64 containers (alu SELs)
        u64 js0 = jsel0 ? d01.y : d01.x;
        u64 js1 = jsel0 ? d23.y : d23.x;
        u64 dxj = jsel1 ? js1 : js0;

        u64 dxii = pack2(dxi, dxi);

        // (m, a) in one FFMA2; splats go to the MOV/alu pipe
        u64 MA = fma2(dxii, C_M_A, HS);
        float m, a; unpack2(MA, m, a);
        u64 mm = pack2(m, m);
        u64 aa = pack2(a, a);

        // t_p = S2[p] + m*dx_j ;  S3[p,k] += t_p * dx_k
        u64 tq = fma2(mm, dxj, S2p);
        float t0, t1; unpack2(tq, t0, t1);
        u64 t0p = pack2(t0, t0);
        u64 t1p = pack2(t1, t1);
        S30[0] = fma2(t0p, d01.x, S30[0]);
        S30[1] = fma2(t0p, d01.y, S30[1]);
        S30[2] = fma2(t0p, d23.x, S30[2]);
        S30[3] = fma2(t0p, d23.y, S30[3]);
        S31[0] = fma2(t1p, d01.x, S31[0]);
        S31[1] = fma2(t1p, d01.y, S31[1]);
        S31[2] = fma2(t1p, d23.x, S31[2]);
        S31[3] = fma2(t1p, d23.y, S31[3]);

        // S2[p] += a*dx_j ;  HS += (0.5,1)*dxi
        S2p = fma2(aa, dxj, S2p);
        HS  = fma2(dxii, C_UPD, HS);
    }

    float S1i;
    { float hh; unpack2(HS, hh, S1i); }

    // chunk S1 from path endpoints (global x, L1/L2-hit)
    u64 S1p[4];
    {
        const int lastrow = (chunk == 3) ? 255 : (first + 64);
        const float* e0 = xp + first * 8;
        const float* e1 = xp + lastrow * 8;
        ulonglong2 a0 = *reinterpret_cast<const ulonglong2*>(e0);
        ulonglong2 a1 = *reinterpret_cast<const ulonglong2*>(e0 + 4);
        ulonglong2 b0v = *reinterpret_cast<const ulonglong2*>(e1);
        ulonglong2 b1v = *reinterpret_cast<const ulonglong2*>(e1 + 4);
        S1p[0] = sub2(b0v.x, a0.x);
        S1p[1] = sub2(b0v.y, a0.y);
        S1p[2] = sub2(b1v.x, a1.x);
        S1p[3] = sub2(b1v.y, a1.y);
    }

    // ===================== 2-round tree combine via smem =====================
    if (chunk == 1) write_sig(&slots[0][0], lane, S30, S31, S2p, S1p);
    if (chunk == 3) write_sig(&slots[1][0], lane, S30, S31, S2p, S1p);
    __syncthreads();
    if (chunk == 0)
        chen_combine(&slots[0][0], lane, i, j0, S30, S31, S2p, S1p, S1i);
    if (chunk == 2)
        chen_combine(&slots[1][0], lane, i, j0, S30, S31, S2p, S1p, S1i);

    if (chunk == 2) write_sig(&slots[1][0], lane, S30, S31, S2p, S1p);
    __syncthreads();
    if (chunk != 0) return;

    chen_combine(&slots[1][0], lane, i, j0, S30, S31, S2p, S1p, S1i);

    // ======================= epilogue: log() + write =======================
    float S1[8];
    unpack2(S1p[0], S1[0], S1[1]);
    unpack2(S1p[1], S1[2], S1[3]);
    unpack2(S1p[2], S1[4], S1[5]);
    unpack2(S1p[3], S1[6], S1[7]);
    float S2a, S2b; unpack2(S2p, S2a, S2b);

    // publish final S1 + S2 grid to slot 0 for cross-lane reads
    float* s0s = &slots[0][0];
    if (lane == 0) {
        *reinterpret_cast<ulonglong2*>(s0s)     = make_ulonglong2(S1p[0], S1p[1]);
        *reinterpret_cast<ulonglong2*>(s0s + 4) = make_ulonglong2(S1p[2], S1p[3]);
    }
    *reinterpret_cast<u64*>(s0s + 8 + 2 * lane) = S2p;
    __syncwarp();

    const float s1i = S1i;                   // == S1[i]
    float2 s1j = *reinterpret_cast<const float2*>(s0s + j0);
    const float s1j0 = s1j.x, s1j1 = s1j.y;

    float* ob = out + (size_t)blockIdx.x * OUT_B;

    // level 1
    if (lane < 8) ob[lane] = s0s[lane];

    // level 2: l2 = S2 - 0.5*S1 (x) S1
    float l2a = fmaf(-0.5f * s1i, s1j0, S2a);
    float l2b = fmaf(-0.5f * s1i, s1j1, S2b);
    *reinterpret_cast<float2*>(ob + 8 + 2 * lane) = make_float2(l2a, l2b);

    // level 3: l3 = S3 - 0.5*(S1 (x) S2 + S2 (x) S1) + (1/3) S1 (x) S1 (x) S1
    const float h  = -0.5f * s1i;
    const float e0 = (1.0f/3.0f) * s1i * s1j0 - 0.5f * S2a;
    const float e1 = (1.0f/3.0f) * s1i * s1j1 - 0.5f * S2b;
    const float* g2 = s0s + 8;

    float l3[16];
    #pragma unroll
    for (int kk = 0; kk < 4; ++kk) {
        float s3a, s3b; unpack2(S30[kk], s3a, s3b);
        int k0 = 2 * kk;
        l3[k0]     = s3a + h * g2[j0*8 + k0]     + e0 * S1[k0];
        l3[k0 + 1] = s3b + h * g2[j0*8 + k0 + 1] + e0 * S1[k0 + 1];
    }
    #pragma unroll
    for (int kk = 0; kk < 4; ++kk) {
        float s3a, s3b; unpack2(S31[kk], s3a, s3b);
        int k0 = 2 * kk;
        l3[8 + k0]     = s3a + h * g2[(j0+1)*8 + k0]     + e1 * S1[k0];
        l3[8 + k0 + 1] = s3b + h * g2[(j0+1)*8 + k0 + 1] + e1 * S1[k0 + 1];
    }

    float* o3 = ob + 72 + 16 * lane;
    #pragma unroll
    for (int v = 0; v < 4; ++v)
        *reinterpret_cast<float4*>(o3 + 4 * v) =
            make_float4(l3[4*v], l3[4*v+1], l3[4*v+2], l3[4*v+3]);
}

extern "C" void kernel_launch(void* const* d_in, const int* in_sizes, int n_in,
                              void* d_out, int out_size)
{
    const float* x = (const float*)d_in[0];
    float* out = (float*)d_out;
    const int B = in_sizes[0] / (L_PATH * D_CH);   // 2048
    logsig_kernel<<<B, NTHREADS>>>(x, out, B);     // 1 path per 128-thread block
}

// round 17
// speedup vs baseline: 1.0426x; 1.0426x over previous
#include <cuda_runtime.h>
#include <cstdint>

typedef unsigned long long u64;

// ---- packed f32x2 helpers (Blackwell sm_100+; FFMA2 only reachable via PTX) ----
__device__ __forceinline__ u64 pack2(float lo, float hi) {
    u64 r; asm("mov.b64 %0, {%1, %2};" : "=l"(r) : "f"(lo), "f"(hi)); return r;
}
__device__ __forceinline__ void unpack2(u64 v, float& lo, float& hi) {
    asm("mov.b64 {%0, %1}, %2;" : "=f"(lo), "=f"(hi) : "l"(v));
}
__device__ __forceinline__ u64 sub2(u64 a, u64 b) {
    u64 r; asm("sub.rn.f32x2 %0, %1, %2;" : "=l"(r) : "l"(a), "l"(b)); return r;
}
__device__ __forceinline__ u64 add2(u64 a, u64 b) {
    u64 r; asm("add.rn.f32x2 %0, %1, %2;" : "=l"(r) : "l"(a), "l"(b)); return r;
}
__device__ __forceinline__ u64 fma2(u64 a, u64 b, u64 c) {
    u64 r; asm("fma.rn.f32x2 %0, %1, %2, %3;" : "=l"(r) : "l"(a), "l"(b), "l"(c)); return r;
}

#define L_PATH 256
#define D_CH   8
#define OUT_B  584   // 8 + 64 + 512
#define SLOT   584   // slot: S1 @0, S2 @8 ([i][j] row-major), S3 @72 ([p][k], p=8i+j)
#define NTHREADS 128
#define SDX_STRIDE 2048          // 255 dx rows + 1 zero pad row = 256*8 floats

// Chen combine: A <- A (x) B, B read from a shared-memory slot.
__device__ __forceinline__ void chen_combine(
    const float* s, int lane, int i, int j0,
    u64 S30[4], u64 S31[4], u64& S2p, u64 S1p[4], float& S1ai)
{
    float S2a0, S2a1; unpack2(S2p, S2a0, S2a1);
    const u64 S2a0p = pack2(S2a0, S2a0);
    const u64 S2a1p = pack2(S2a1, S2a1);
    const u64 S1aip = pack2(S1ai, S1ai);

    ulonglong2 t0 = *reinterpret_cast<const ulonglong2*>(s);
    ulonglong2 t1 = *reinterpret_cast<const ulonglong2*>(s + 4);
    u64 S1bp[4] = {t0.x, t0.y, t1.x, t1.y};

    const float* rj = s + 8 + j0 * 8;
    ulonglong2 u0 = *reinterpret_cast<const ulonglong2*>(rj);
    ulonglong2 u1 = *reinterpret_cast<const ulonglong2*>(rj + 4);
    ulonglong2 v0 = *reinterpret_cast<const ulonglong2*>(rj + 8);
    ulonglong2 v1 = *reinterpret_cast<const ulonglong2*>(rj + 12);
    u64 Bj0[4] = {u0.x, u0.y, u1.x, u1.y};
    u64 Bj1[4] = {v0.x, v0.y, v1.x, v1.y};

    float2 s2bi = *reinterpret_cast<const float2*>(s + 8 + i * 8 + j0);
    float2 s1bj = *reinterpret_cast<const float2*>(s + j0);
    float  s1bi = s[i];

    const float* q = s + 72 + 16 * lane;
    ulonglong2 q0 = *reinterpret_cast<const ulonglong2*>(q);
    ulonglong2 q1 = *reinterpret_cast<const ulonglong2*>(q + 4);
    ulonglong2 q2 = *reinterpret_cast<const ulonglong2*>(q + 8);
    ulonglong2 q3 = *reinterpret_cast<const ulonglong2*>(q + 12);
    u64 Q0[4] = {q0.x, q0.y, q1.x, q1.y};
    u64 Q1[4] = {q2.x, q2.y, q3.x, q3.y};

    // S3 = S3a + S3b + S2a (x) S1b + S1a (x) S2b   (pre-update S2a, S1a)
    #pragma unroll
    for (int kk = 0; kk < 4; ++kk) {
        S30[kk] = add2(S30[kk], Q0[kk]);
        S30[kk] = fma2(S2a0p, S1bp[kk], S30[kk]);
        S30[kk] = fma2(S1aip, Bj0[kk], S30[kk]);
        S31[kk] = add2(S31[kk], Q1[kk]);
        S31[kk] = fma2(S2a1p, S1bp[kk], S31[kk]);
        S31[kk] = fma2(S1aip, Bj1[kk], S31[kk]);
    }
    S2p = add2(S2p, pack2(s2bi.x, s2bi.y));
    S2p = fma2(S1aip, pack2(s1bj.x, s1bj.y), S2p);
    #pragma unroll
    for (int kk = 0; kk < 4; ++kk) S1p[kk] = add2(S1p[kk], S1bp[kk]);
    S1ai += s1bi;
}

__device__ __forceinline__ void write_sig(
    float* s, int lane,
    const u64 S30[4], const u64 S31[4], u64 S2p, const u64 S1p[4])
{
    if (lane == 0) {
        *reinterpret_cast<ulonglong2*>(s)     = make_ulonglong2(S1p[0], S1p[1]);
        *reinterpret_cast<ulonglong2*>(s + 4) = make_ulonglong2(S1p[2], S1p[3]);
    }
    *reinterpret_cast<u64*>(s + 8 + 2 * lane) = S2p;
    float* q = s + 72 + 16 * lane;
    *reinterpret_cast<ulonglong2*>(q)      = make_ulonglong2(S30[0], S30[1]);
    *reinterpret_cast<ulonglong2*>(q + 4)  = make_ulonglong2(S30[2], S30[3]);
    *reinterpret_cast<ulonglong2*>(q + 8)  = make_ulonglong2(S31[0], S31[1]);
    *reinterpret_cast<ulonglong2*>(q + 12) = make_ulonglong2(S31[2], S31[3]);
}

// 128 threads = 4 warps = 1 path split into 4 chunks of 64 steps
// (row 255 is a staged zero row -> identity Chen step, uniform trip count).
// Hot loop: 12 FFMA2 + 3 LDS per step; dxj from row regs (alu SELs); unroll 8.
__global__ void __launch_bounds__(NTHREADS, 8)
logsig_kernel(const float* __restrict__ x, float* __restrict__ out, int B)
{
    __shared__ float sdx[SDX_STRIDE];    // 8 KB: dx rows for this path (+ zero row)
    __shared__ float slots[2][SLOT];     // 4.7 KB: combine slots

    const int tid   = threadIdx.x;
    const int chunk = tid >> 5;          // warp == chunk 0..3
    const int lane  = tid & 31;
    const int i  = lane >> 2;
    const int j0 = (lane & 3) << 1;
    const bool jsel0 = (lane & 1) != 0;  // dxj select predicates (hoisted)
    const bool jsel1 = (lane & 2) != 0;

    const float* __restrict__ xp = x + (size_t)blockIdx.x * (L_PATH * D_CH);

    // ============ stage increments dx[t] = x[t+1]-x[t] into smem (coalesced) ============
    #pragma unroll
    for (int q = 0; q < 4; ++q) {
        int r = tid + q * NTHREADS;       // 0..509 (last iter partially masked)
        if (r < 510) {
            int t = r >> 1;
            int h = (r & 1) << 2;
            const float* src = xp + t * 8 + h;
            float4 b = *reinterpret_cast<const float4*>(src + 8);
            float4 a = *reinterpret_cast<const float4*>(src);
            *reinterpret_cast<float4*>(&sdx[t * 8 + h]) =
                make_float4(b.x - a.x, b.y - a.y, b.z - a.z, b.w - a.w);
        }
    }
    if (tid < 2)                          // zero pad row t=255 (identity step)
        *reinterpret_cast<float4*>(&sdx[2040 + tid * 4]) = make_float4(0.f, 0.f, 0.f, 0.f);
    __syncthreads();

    // ======================= chunk signature (Chen recursion) =======================
    const int first = chunk * 64;
    const float* sp = &sdx[first * 8];

    // HS = (0.5*S1_i, S1_i) packed: one register holds the whole scalar side chain.
    const u64 C_M_A = pack2(1.0f/6.0f, 0.5f);   // MA = (m, a) = (h+dxi/6, S1+dxi/2)
    const u64 C_UPD = pack2(0.5f, 1.0f);        // HS += (0.5, 1)*dxi
    u64 HS    = 0ull;
    u64 S2p   = 0ull;
    u64 S30[4] = {0ull,0ull,0ull,0ull};
    u64 S31[4] = {0ull,0ull,0ull,0ull};

    #pragma unroll 8
    for (int t = 0; t < 64; ++t) {
        const float* row = sp + t * 8;
        ulonglong2 d01 = *reinterpret_cast<const ulonglong2*>(row);
        ulonglong2 d23 = *reinterpret_cast<const ulonglong2*>(row + 4);
        float dxi = row[i];                           // LDS.32 (1 wavefront)

        // dxj = (row[j0], row[j0+1]) — one of the four loaded u64 containers (alu SELs)
        u64 js0 = jsel0 ? d01.y : d01.x;
        u64 js1 = jsel0 ? d23.y : d23.x;
        u64 dxj = jsel1 ? js1 : js0;

        u64 dxii = pack2(dxi, dxi);

        // (m, a) in one FFMA2; splats go to the MOV/alu pipe
        u64 MA = fma2(dxii, C_M_A, HS);
        float m, a; unpack2(MA, m, a);
        u64 mm = pack2(m, m);
        u64 aa = pack2(a, a);

        // t_p = S2[p] + m*dx_j ;  S3[p,k] += t_p * dx_k
        u64 tq = fma2(mm, dxj, S2p);
        float t0, t1; unpack2(tq, t0, t1);
        u64 t0p = pack2(t0, t0);
        u64 t1p = pack2(t1, t1);
        S30[0] = fma2(t0p, d01.x, S30[0]);
        S30[1] = fma2(t0p, d01.y, S30[1]);
        S30[2] = fma2(t0p, d23.x, S30[2]);
        S30[3] = fma2(t0p, d23.y, S30[3]);
        S31[0] = fma2(t1p, d01.x, S31[0]);
        S31[1] = fma2(t1p, d01.y, S31[1]);
        S31[2] = fma2(t1p, d23.x, S31[2]);
        S31[3] = fma2(t1p, d23.y, S31[3]);

        // S2[p] += a*dx_j ;  HS += (0.5,1)*dxi
        S2p = fma2(aa, dxj, S2p);
        HS  = fma2(dxii, C_UPD, HS);
    }

    float S1i;
    { float hh; unpack2(HS, hh, S1i); }

    // chunk S1 from path endpoints (global x, L1/L2-hit)
    u64 S1p[4];
    {
        const int lastrow = (chunk == 3) ? 255 : (first + 64);
        const float* e0 = xp + first * 8;
        const float* e1 = xp + lastrow * 8;
        ulonglong2 a0 = *reinterpret_cast<const ulonglong2*>(e0);
        ulonglong2 a1 = *reinterpret_cast<const ulonglong2*>(e0 + 4);
        ulonglong2 b0v = *reinterpret_cast<const ulonglong2*>(e1);
        ulonglong2 b1v = *reinterpret_cast<const ulonglong2*>(e1 + 4);
        S1p[0] = sub2(b0v.x, a0.x);
        S1p[1] = sub2(b0v.y, a0.y);
        S1p[2] = sub2(b1v.x, a1.x);
        S1p[3] = sub2(b1v.y, a1.y);
    }

    // ===================== 2-round tree combine via smem =====================
    if (chunk == 1) write_sig(&slots[0][0], lane, S30, S31, S2p, S1p);
    if (chunk == 3) write_sig(&slots[1][0], lane, S30, S31, S2p, S1p);
    __syncthreads();
    if (chunk == 0)
        chen_combine(&slots[0][0], lane, i, j0, S30, S31, S2p, S1p, S1i);
    if (chunk == 2)
        chen_combine(&slots[1][0], lane, i, j0, S30, S31, S2p, S1p, S1i);

    if (chunk == 2) write_sig(&slots[1][0], lane, S30, S31, S2p, S1p);
    __syncthreads();
    if (chunk != 0) return;

    chen_combine(&slots[1][0], lane, i, j0, S30, S31, S2p, S1p, S1i);

    // ======================= epilogue: log() + write =======================
    float S1[8];
    unpack2(S1p[0], S1[0], S1[1]);
    unpack2(S1p[1], S1[2], S1[3]);
    unpack2(S1p[2], S1[4], S1[5]);
    unpack2(S1p[3], S1[6], S1[7]);
    float S2a, S2b; unpack2(S2p, S2a, S2b);

    // publish final S1 + S2 grid to slot 0 for cross-lane reads
    float* s0s = &slots[0][0];
    if (lane == 0) {
        *reinterpret_cast<ulonglong2*>(s0s)     = make_ulonglong2(S1p[0], S1p[1]);
        *reinterpret_cast<ulonglong2*>(s0s + 4) = make_ulonglong2(S1p[2], S1p[3]);
    }
    *reinterpret_cast<u64*>(s0s + 8 + 2 * lane) = S2p;
    __syncwarp();

    const float s1i = S1i;                   // == S1[i]
    float2 s1j = *reinterpret_cast<const float2*>(s0s + j0);
    const float s1j0 = s1j.x, s1j1 = s1j.y;

    float* ob = out + (size_t)blockIdx.x * OUT_B;

    // level 1
    if (lane < 8) ob[lane] = s0s[lane];

    // level 2: l2 = S2 - 0.5*S1 (x) S1
    float l2a = fmaf(-0.5f * s1i, s1j0, S2a);
    float l2b = fmaf(-0.5f * s1i, s1j1, S2b);
    *reinterpret_cast<float2*>(ob + 8 + 2 * lane) = make_float2(l2a, l2b);

    // level 3: l3 = S3 - 0.5*(S1 (x) S2 + S2 (x) S1) + (1/3) S1 (x) S1 (x) S1
    const float h  = -0.5f * s1i;
    const float e0 = (1.0f/3.0f) * s1i * s1j0 - 0.5f * S2a;
    const float e1 = (1.0f/3.0f) * s1i * s1j1 - 0.5f * S2b;
    const float* g2 = s0s + 8;

    float l3[16];
    #pragma unroll
    for (int kk = 0; kk < 4; ++kk) {
        float s3a, s3b; unpack2(S30[kk], s3a, s3b);
        int k0 = 2 * kk;
        l3[k0]     = s3a + h * g2[j0*8 + k0]     + e0 * S1[k0];
        l3[k0 + 1] = s3b + h * g2[j0*8 + k0 + 1] + e0 * S1[k0 + 1];
    }
    #pragma unroll
    for (int kk = 0; kk < 4; ++kk) {
        float s3a, s3b; unpack2(S31[kk], s3a, s3b);
        int k0 = 2 * kk;
        l3[8 + k0]     = s3a + h * g2[(j0+1)*8 + k0]     + e1 * S1[k0];
        l3[8 + k0 + 1] = s3b + h * g2[(j0+1)*8 + k0 + 1] + e1 * S1[k0 + 1];
    }

    float* o3 = ob + 72 + 16 * lane;
    #pragma unroll
    for (int v = 0; v < 4; ++v)
        *reinterpret_cast<float4*>(o3 + 4 * v) =
            make_float4(l3[4*v], l3[4*v+1], l3[4*v+2], l3[4*v+3]);
}

extern "C" void kernel_launch(void* const* d_in, const int* in_sizes, int n_in,
                              void* d_out, int out_size)
{
    const float* x = (const float*)d_in[0];
    float* out = (float*)d_out;
    const int B = in_sizes[0] / (L_PATH * D_CH);   // 2048
    logsig_kernel<<<B, NTHREADS>>>(x, out, B);     // 1 path per 128-thread block
}